// round 6
// baseline (speedup 1.0000x reference)
#include <cuda_runtime.h>
#include <math.h>

// Problem constants
#define B   256
#define L   512
#define I   32
#define H   16
#define G   64            // 4*H gates
#define NT  511           // number of increments
#define SIGD 4368         // H + H^2 + H^3
#define O   10

// Scratch (device globals; no allocation allowed)
static __device__ float g_xw[B * L * G];        // 33.5 MB : input projection + biases
static __device__ float g_d [B * NT * H];       // 8.4 MB  : h increments d_t = h_{t+1}-h_t

// ---------------------------------------------------------------------------
// Activations via hardware MUFU.TANH: lat 16 vs ~40-45 for exp-based.
// sigmoid(x) = 0.5*tanh(x/2) + 0.5  (exact identity; only tanh is approx)
// ---------------------------------------------------------------------------
__device__ __forceinline__ float tanh_hw(float x) {
    float y; asm("tanh.approx.f32 %0, %1;" : "=f"(y) : "f"(x)); return y;
}
__device__ __forceinline__ float sigmoid_hw(float x) {
    return fmaf(tanh_hw(0.5f * x), 0.5f, 0.5f);
}

// ---------------------------------------------------------------------------
// Packed fp32x2 helpers (Blackwell FFMA2 via PTX) — sig kernel only
// ---------------------------------------------------------------------------
typedef unsigned long long u64t;
__device__ __forceinline__ u64t pack2_(float lo, float hi) {
    u64t r; asm("mov.b64 %0, {%1, %2};" : "=l"(r) : "f"(lo), "f"(hi)); return r;
}
__device__ __forceinline__ void unpack2_(u64t v, float& lo, float& hi) {
    asm("mov.b64 {%0, %1}, %2;" : "=f"(lo), "=f"(hi) : "l"(v));
}
__device__ __forceinline__ u64t ffma2_(u64t a, u64t b, u64t c) {
    u64t d; asm("fma.rn.f32x2 %0, %1, %2, %3;" : "=l"(d) : "l"(a), "l"(b), "l"(c));
    return d;
}

// ---------------------------------------------------------------------------
// K1: xw[bt][g] = b_ih[g] + b_hh[g] + sum_i X[bt][i] * W_ih[g][i]
// (measured 28.5us — unchanged)
// ---------------------------------------------------------------------------
__global__ void __launch_bounds__(256) xw_kernel(const float* __restrict__ X,
                                                 const float* __restrict__ Wih,
                                                 const float* __restrict__ bih,
                                                 const float* __restrict__ bhh) {
    __shared__ float Xs[64 * 33];
    __shared__ float Ws[32 * 65];
    __shared__ float bs[64];

    int tid = threadIdx.x;
    int bt0 = blockIdx.x * 64;
    const float* Xg = X + (size_t)bt0 * I;

    for (int i = tid; i < 64 * I; i += 256) {
        int r = i >> 5, k = i & 31;
        Xs[r * 33 + k] = Xg[i];
        Ws[k * 65 + r] = Wih[i];
    }
    if (tid < 64) bs[tid] = bih[tid] + bhh[tid];
    __syncthreads();

    int tg = tid & 15;
    int tb = tid >> 4;
    float acc[4][4];
#pragma unroll
    for (int bi = 0; bi < 4; bi++)
#pragma unroll
        for (int gi = 0; gi < 4; gi++)
            acc[bi][gi] = bs[tg * 4 + gi];

#pragma unroll 8
    for (int k = 0; k < I; k++) {
        float xv[4], wv[4];
#pragma unroll
        for (int bi = 0; bi < 4; bi++) xv[bi] = Xs[(tb * 4 + bi) * 33 + k];
#pragma unroll
        for (int gi = 0; gi < 4; gi++) wv[gi] = Ws[k * 65 + tg * 4 + gi];
#pragma unroll
        for (int bi = 0; bi < 4; bi++)
#pragma unroll
            for (int gi = 0; gi < 4; gi++)
                acc[bi][gi] = fmaf(xv[bi], wv[gi], acc[bi][gi]);
    }

#pragma unroll
    for (int bi = 0; bi < 4; bi++) {
        int bt = bt0 + tb * 4 + bi;
        float4 v = make_float4(acc[bi][0], acc[bi][1], acc[bi][2], acc[bi][3]);
        *reinterpret_cast<float4*>(g_xw + (size_t)bt * G + tg * 4) = v;
    }
}

// ---------------------------------------------------------------------------
// K2: LSTM recurrence. One warp per batch element.
// Lane l computes gate rows l and l+32 (lanes<16: i,g ; lanes>=16: f,o).
// NEW: h broadcast by feeding __shfl_sync(hn, j) straight into the dot FMAs
// (no smem, no syncwarp on the critical path). 4-deep xw prefetch.
// Writes increments d_t = h_{t+1} - h_t.
// ---------------------------------------------------------------------------
__global__ void __launch_bounds__(128) lstm_kernel(const float* __restrict__ Whh) {
    int lane = threadIdx.x & 31;
    int warp = threadIdx.x >> 5;
    int b = blockIdx.x * 4 + warp;

    float w0[H], w1[H];
#pragma unroll
    for (int j = 0; j < H; j++) {
        w0[j] = __ldg(Whh + lane * H + j);
        w1[j] = __ldg(Whh + (lane + 32) * H + j);
    }
    float hn = 0.f;            // this lane's h_j (valid for lanes < 16; h0 = 0)
    float c = 0.f, hprev = 0.f;

    const float* xp = g_xw + (size_t)b * (L * G) + lane;
    float* dp = g_d + (size_t)b * (NT * H);

    float bx0[4], bx1[4];
#pragma unroll
    for (int k = 0; k < 4; k++) { bx0[k] = xp[k * G]; bx1[k] = xp[k * G + 32]; }

#pragma unroll 4
    for (int t = 0; t < L; t++) {
        int slot = t & 3;
        float a0 = bx0[slot], a1 = bx1[slot];
        if (t + 4 < L) { bx0[slot] = xp[(t + 4) * G]; bx1[slot] = xp[(t + 4) * G + 32]; }

        float q0 = 0.f, q1 = 0.f;
#pragma unroll
        for (int j = 0; j < H; j += 2) {
            float hj0 = __shfl_sync(0xffffffffu, hn, j);
            float hj1 = __shfl_sync(0xffffffffu, hn, j + 1);
            a0 = fmaf(hj0, w0[j],     a0);
            q0 = fmaf(hj1, w0[j + 1], q0);
            a1 = fmaf(hj0, w1[j],     a1);
            q1 = fmaf(hj1, w1[j + 1], q1);
        }
        a0 += q0; a1 += q1;

        float fg = __shfl_down_sync(0xffffffffu, a0, 16);  // lanes<16: f preact
        float og = __shfl_down_sync(0xffffffffu, a1, 16);  // lanes<16: o preact

        float si = sigmoid_hw(a0);
        float sf = sigmoid_hw(fg);
        float so = sigmoid_hw(og);
        float tg = tanh_hw(a1);
        c = fmaf(sf, c, si * tg);
        hn = so * tanh_hw(c);   // garbage on lanes>=16 (never used as shfl src)

        if (lane < H) {
            if (t) dp[(t - 1) * H + lane] = hn - hprev;
            hprev = hn;
        }
    }
}

// ---------------------------------------------------------------------------
// K3: depth-3 signature scan + fused FC epilogue. One 256-thread CTA / batch.
// Thread tid = (a,b): S2[a][b] scalar, S3[a][b][0..15] as 8 packed f32x2.
// NEW: increment rows loaded directly as ulonglong2 (no pack movs).
// ---------------------------------------------------------------------------
__global__ void __launch_bounds__(256) sig_kernel(const float* __restrict__ fcw,
                                                  const float* __restrict__ fcb,
                                                  float* __restrict__ out) {
    __shared__ __align__(16) float ds[NT * H];   // 32704 B
    __shared__ float red[8][O];
    int bidx = blockIdx.x;
    int tid = threadIdx.x;

    {
        const float4* s4 = reinterpret_cast<const float4*>(g_d + (size_t)bidx * (NT * H));
        float4* t4 = reinterpret_cast<float4*>(ds);
        for (int i = tid; i < (NT * H) / 4; i += 256) t4[i] = s4[i];
    }
    __syncthreads();

    int a  = tid >> 4;
    int bb = tid & 15;

    float S1h = 0.f, S2 = 0.f;       // S1h = S1/2 (exact scaling)
    u64t S3p[8];
#pragma unroll
    for (int j = 0; j < 8; j++) S3p[j] = 0ull;

#pragma unroll 2
    for (int t = 0; t < NT; t++) {
        const float* dr = ds + t * H;
        ulonglong2 p0 = *reinterpret_cast<const ulonglong2*>(dr);
        ulonglong2 p1 = *reinterpret_cast<const ulonglong2*>(dr + 4);
        ulonglong2 p2 = *reinterpret_cast<const ulonglong2*>(dr + 8);
        ulonglong2 p3 = *reinterpret_cast<const ulonglong2*>(dr + 12);
        float da = dr[a];
        float db = dr[bb];

        float m1   = da * db;
        float db2  = db + db;
        float coef = fmaf(S1h, db, fmaf(m1, (1.f / 6.f), S2));
        u64t cp = pack2_(coef, coef);

        S3p[0] = ffma2_(cp, p0.x, S3p[0]);
        S3p[1] = ffma2_(cp, p0.y, S3p[1]);
        S3p[2] = ffma2_(cp, p1.x, S3p[2]);
        S3p[3] = ffma2_(cp, p1.y, S3p[3]);
        S3p[4] = ffma2_(cp, p2.x, S3p[4]);
        S3p[5] = ffma2_(cp, p2.y, S3p[5]);
        S3p[6] = ffma2_(cp, p3.x, S3p[6]);
        S3p[7] = ffma2_(cp, p3.y, S3p[7]);

        S2  = fmaf(S1h, db2, fmaf(0.5f, m1, S2));
        S1h = fmaf(0.5f, da, S1h);
    }

    // ---- fused FC: out[b][o] = sig . fc_w[o] + fc_b[o] ----
    float S3[16];
#pragma unroll
    for (int j = 0; j < 8; j++) unpack2_(S3p[j], S3[2 * j], S3[2 * j + 1]);
    float S1 = S1h + S1h;

    float part[O];
#pragma unroll
    for (int o = 0; o < O; o++) {
        const float* wr = fcw + (size_t)o * SIGD;
        float acc = S2 * __ldg(wr + H + tid);              // level-2 term
        if (bb == 0) acc = fmaf(S1, __ldg(wr + a), acc);   // level-1 term
        const float4* w4 = reinterpret_cast<const float4*>(wr + H + H * H + tid * 16);
#pragma unroll
        for (int j = 0; j < 4; j++) {
            float4 w = __ldg(w4 + j);
            acc = fmaf(S3[4 * j + 0], w.x, acc);
            acc = fmaf(S3[4 * j + 1], w.y, acc);
            acc = fmaf(S3[4 * j + 2], w.z, acc);
            acc = fmaf(S3[4 * j + 3], w.w, acc);
        }
        part[o] = acc;
    }

    int lane = tid & 31, warp = tid >> 5;
#pragma unroll
    for (int off = 16; off > 0; off >>= 1)
#pragma unroll
        for (int o = 0; o < O; o++)
            part[o] += __shfl_down_sync(0xffffffffu, part[o], off);
    if (lane == 0)
#pragma unroll
        for (int o = 0; o < O; o++) red[warp][o] = part[o];
    __syncthreads();

    if (tid < O) {
        float v = fcb[tid];
#pragma unroll
        for (int w = 0; w < 8; w++) v += red[w][tid];
        out[bidx * O + tid] = v;
    }
}

// ---------------------------------------------------------------------------
extern "C" void kernel_launch(void* const* d_in, const int* in_sizes, int n_in,
                              void* d_out, int out_size) {
    const float* X   = (const float*)d_in[0];
    const float* Wih = (const float*)d_in[1];
    const float* Whh = (const float*)d_in[2];
    const float* bih = (const float*)d_in[3];
    const float* bhh = (const float*)d_in[4];
    const float* fcw = (const float*)d_in[5];
    const float* fcb = (const float*)d_in[6];
    float* out = (float*)d_out;

    xw_kernel<<<(B * L) / 64, 256>>>(X, Wih, bih, bhh);
    lstm_kernel<<<B / 4, 128>>>(Whh);
    sig_kernel<<<B, 256>>>(fcw, fcb, out);
}